// round 15
// baseline (speedup 1.0000x reference)
#include <cuda_runtime.h>
#include <cuda_bf16.h>
#include <math.h>
#include <stdint.h>

#define HW 262144       // 512*512
#define SLABPX 33792    // 66*512 pixels per conv slab buffer (incl. halo rows)
typedef unsigned long long u64;

// ---------------- packed f32x2 helpers (sm_103a FFMA2) ------------------------
__device__ __forceinline__ u64 pk(float lo, float hi) {
    u64 r;
    asm("mov.b64 %0, {%1, %2};" : "=l"(r) : "f"(lo), "f"(hi));
    return r;
}
__device__ __forceinline__ void fma2(u64& d, u64 a, u64 b) {
    asm("fma.rn.f32x2 %0, %1, %2, %0;" : "+l"(d) : "l"(a), "l"(b));
}
__device__ __forceinline__ float2 upk(u64 v) {
    float2 f;
    asm("mov.b64 {%0, %1}, %2;" : "=f"(f.x), "=f"(f.y) : "l"(v));
    return f;
}

// ---------------- mma.sync helper (bf16, fp32 accum) --------------------------
__device__ __forceinline__ void mma16816(float* c, const uint32_t* a, const uint32_t* b) {
    asm volatile(
        "mma.sync.aligned.m16n8k16.row.col.f32.bf16.bf16.f32 "
        "{%0,%1,%2,%3}, {%4,%5,%6,%7}, {%8,%9}, {%0,%1,%2,%3};"
        : "+f"(c[0]), "+f"(c[1]), "+f"(c[2]), "+f"(c[3])
        : "r"(a[0]), "r"(a[1]), "r"(a[2]), "r"(a[3]), "r"(b[0]), "r"(b[1]));
}
__device__ __forceinline__ uint32_t pack_bf16x2(float a, float b) {
    return (uint32_t)__bfloat16_as_ushort(__float2bfloat16(a))
         | ((uint32_t)__bfloat16_as_ushort(__float2bfloat16(b)) << 16);
}

// ---------------- scratch (device globals; no allocation allowed) -------------
__device__ float g_cbuf  [2*144*SLABPX];// conv slab ring (38.9 MB, L2-resident)
__device__ float g_dwo   [2*144*HW];    // after depthwise 3x3 (q,k,v)
__device__ float g_ao    [2*48*HW];     // attn @ v, image layout
__device__ float g_sq    [2*2*48*16];   // sum of squares: [b][q/k][ch][phase]
__device__ float g_gsplit[32*16*96*96]; // per-split partial grams
__device__ __nv_bfloat16 g_attn_h[16*96*96];  // softmaxed attn hi, row-major [r][d]
__device__ __nv_bfloat16 g_attn_l[16*96*96];  // softmaxed attn lo

// ---------------- zero sum-of-squares accumulator -----------------------------
__global__ void k_zero() {
    int i = blockIdx.x * 256 + threadIdx.x;
    if (i < 2*2*48*16) g_sq[i] = 0.f;
}

// ---------------- qkv 1x1 conv via mma.sync, one 66-row slab ------------------
// grid (132, 2), block 288 (9 warps = 9 oc-tiles of 16).  N = 256 px per CTA.
#define CPW 28                               // padded words per K row (24 used)
#define C_WH 0
#define C_WL (144*CPW)
#define C_XH (2*144*CPW)
#define C_XL (2*144*CPW + 256*CPW)
#define CONV_SMEM ((2*144*CPW + 2*256*CPW)*4)  // 89600 bytes

__global__ __launch_bounds__(288) void k_conv_slab(const float* __restrict__ x,
                                                   const float* __restrict__ wgt,
                                                   int slab) {
    extern __shared__ uint32_t swc[];
    const int tid = threadIdx.x;
    const int wid = tid >> 5, lane = tid & 31;
    const int px0 = blockIdx.x * 256;        // local pixel base in slab (66 rows)
    const int b   = blockIdx.y;
    const float* inb = x + (size_t)b * 48 * HW;

    // A fill: weights [144][48] -> hi/lo bf16, row-major padded
    {
        __nv_bfloat16* wh = (__nv_bfloat16*)(swc + C_WH);
        __nv_bfloat16* wl = (__nv_bfloat16*)(swc + C_WL);
        for (int i = tid; i < 144*48; i += 288) {
            int oc = i / 48, ci = i - oc*48;
            float v = wgt[i];
            __nv_bfloat16 hi = __float2bfloat16(v);
            wh[oc*(2*CPW) + ci] = hi;
            wl[oc*(2*CPW) + ci] = __float2bfloat16(v - __bfloat162float(hi));
        }
    }
    // B fill: x tile [48 ch][256 px] -> [px][ch] hi/lo bf16 (clamped global rows)
    {
        __nv_bfloat16* xh = (__nv_bfloat16*)(swc + C_XH);
        __nv_bfloat16* xl = (__nv_bfloat16*)(swc + C_XL);
        for (int i = tid; i < 48*64; i += 288) {
            int ch = i >> 6, p4 = i & 63;
            int p = px0 + p4*4;                        // local pixel (row-aligned)
            int gr = 64*slab - 1 + (p >> 9);           // global row (-1 halo)
            gr = min(max(gr, 0), 511);
            float4 v4 = *(const float4*)(inb + (size_t)ch*HW + gr*512 + (p & 511));
            float vv[4] = {v4.x, v4.y, v4.z, v4.w};
#pragma unroll
            for (int t = 0; t < 4; t++) {
                float v = vv[t];
                __nv_bfloat16 hi = __float2bfloat16(v);
                xh[(p4*4 + t)*(2*CPW) + ch] = hi;
                xl[(p4*4 + t)*(2*CPW) + ch] = __float2bfloat16(v - __bfloat162float(hi));
            }
        }
    }
    __syncthreads();

    const int g4 = lane >> 2, q4 = lane & 3;
    const int arow = wid*16 + g4;

#pragma unroll 1
    for (int half = 0; half < 2; half++) {
        float acc[16][4];
#pragma unroll
        for (int t = 0; t < 16; t++)
#pragma unroll
            for (int i = 0; i < 4; i++) acc[t][i] = 0.f;

#pragma unroll
        for (int ks = 0; ks < 3; ks++) {
            const int kw = ks*8 + q4;
            uint32_t Ah[4], Al[4];
            Ah[0] = swc[C_WH +  arow     *CPW + kw    ];
            Ah[1] = swc[C_WH + (arow + 8)*CPW + kw    ];
            Ah[2] = swc[C_WH +  arow     *CPW + kw + 4];
            Ah[3] = swc[C_WH + (arow + 8)*CPW + kw + 4];
            Al[0] = swc[C_WL +  arow     *CPW + kw    ];
            Al[1] = swc[C_WL + (arow + 8)*CPW + kw    ];
            Al[2] = swc[C_WL +  arow     *CPW + kw + 4];
            Al[3] = swc[C_WL + (arow + 8)*CPW + kw + 4];
#pragma unroll
            for (int nt = 0; nt < 16; nt++) {
                const int nrow = (half*16 + nt)*8 + g4;
                uint32_t Bh[2], Bl[2];
                Bh[0] = swc[C_XH + nrow*CPW + kw    ];
                Bh[1] = swc[C_XH + nrow*CPW + kw + 4];
                Bl[0] = swc[C_XL + nrow*CPW + kw    ];
                Bl[1] = swc[C_XL + nrow*CPW + kw + 4];
                mma16816(acc[nt], Ah, Bh);
                mma16816(acc[nt], Ah, Bl);
                mma16816(acc[nt], Al, Bh);
            }
        }
#pragma unroll
        for (int nt = 0; nt < 16; nt++) {
            const int col = px0 + (half*16 + nt)*8 + q4*2;
            float* o1 = g_cbuf + ((size_t)b*144 + arow)*SLABPX + col;
            *(float2*)o1 = make_float2(acc[nt][0], acc[nt][1]);
            *(float2*)(o1 + (size_t)8*SLABPX) = make_float2(acc[nt][2], acc[nt][3]);
        }
    }
}

// ---------------- 1x1 conv as SGEMM (f32x2) — used for proj -------------------
__global__ __launch_bounds__(128) void k_conv1x1(const float* __restrict__ in,
                                                 const float* __restrict__ wgt,
                                                 float* __restrict__ out,
                                                 int ocTot) {
    __shared__ __align__(16) float s_x[48*128];
    __shared__ float s_w[48*48];
    const int tid = threadIdx.x;
    const int px0 = blockIdx.x * 128;
    const int ocb = blockIdx.y * 48;
    const int b   = blockIdx.z;
    const float* inb = in + (size_t)b * 48 * HW;

    for (int i = tid; i < 48*48; i += 128) {
        int oc = i / 48, ci = i - oc*48;
        s_w[ci*48 + oc] = wgt[(ocb + oc)*48 + ci];
    }
    for (int i = tid; i < 48*32; i += 128) {
        int ci = i >> 5, p4 = i & 31;
        ((float4*)s_x)[i] = ((const float4*)(inb + (size_t)ci*HW + px0))[p4];
    }
    __syncthreads();

    const int ty = tid >> 4, tx = tid & 15;
    u64 acc2[6][4];
#pragma unroll
    for (int i = 0; i < 6; i++)
#pragma unroll
        for (int j = 0; j < 4; j++) acc2[i][j] = pk(0.f, 0.f);

    for (int ci = 0; ci < 48; ci++) {
        u64 wp[6], xv[4];
#pragma unroll
        for (int i = 0; i < 6; i++) {
            float wv = s_w[ci*48 + ty*6 + i];
            wp[i] = pk(wv, wv);
        }
#pragma unroll
        for (int j = 0; j < 4; j++)
            xv[j] = *(const u64*)&s_x[ci*128 + tx*2 + j*32];
#pragma unroll
        for (int i = 0; i < 6; i++)
#pragma unroll
            for (int j = 0; j < 4; j++) fma2(acc2[i][j], wp[i], xv[j]);
    }

#pragma unroll
    for (int i = 0; i < 6; i++) {
        float* op = out + ((size_t)b*ocTot + ocb + ty*6 + i)*HW + px0;
#pragma unroll
        for (int j = 0; j < 4; j++)
            *(float2*)(op + tx*2 + j*32) = upk(acc2[i][j]);
    }
}

// ---------------- depthwise 3x3 slab (reads conv ring) + fused norms ----------
// grid (64, 144, 2), block 128
__global__ __launch_bounds__(128) void k_dw_slab(const float* __restrict__ dww,
                                                 int slab) {
    __shared__ float s_red[4][4];
    const int y  = 64*slab + blockIdx.x;     // global output row
    const int ch = blockIdx.y;
    const int b  = blockIdx.z;
    const float* in  = g_cbuf + (size_t)(b*144 + ch) * SLABPX;
    float*       out = g_dwo  + (size_t)(b*144 + ch) * HW;
    float w[9];
#pragma unroll
    for (int i = 0; i < 9; i++) w[i] = dww[ch*9 + i];

    const int x4 = threadIdx.x * 4;
    float o0 = 0.f, o1 = 0.f, o2 = 0.f, o3 = 0.f;
#pragma unroll
    for (int dy = -1; dy <= 1; dy++) {
        int yy = y + dy;
        if (yy < 0 || yy >= 512) continue;
        const float* row = in + (yy - 64*slab + 1)*512;   // local slab row
        float4 c = *(const float4*)(row + x4);
        float l = (x4 > 0)   ? row[x4 - 1] : 0.f;
        float r = (x4 < 508) ? row[x4 + 4] : 0.f;
        float w0 = w[(dy+1)*3], w1 = w[(dy+1)*3 + 1], w2 = w[(dy+1)*3 + 2];
        o0 += w0*l   + w1*c.x + w2*c.y;
        o1 += w0*c.x + w1*c.y + w2*c.z;
        o2 += w0*c.y + w1*c.z + w2*c.w;
        o3 += w0*c.z + w1*c.w + w2*r;
    }
    *(float4*)(out + y*512 + x4) = make_float4(o0, o1, o2, o3);

    if (ch < 96) {
        float s0 = o0*o0, s1 = o1*o1, s2 = o2*o2, s3 = o3*o3;
#pragma unroll
        for (int o = 16; o > 0; o >>= 1) {
            s0 += __shfl_xor_sync(0xffffffffu, s0, o);
            s1 += __shfl_xor_sync(0xffffffffu, s1, o);
            s2 += __shfl_xor_sync(0xffffffffu, s2, o);
            s3 += __shfl_xor_sync(0xffffffffu, s3, o);
        }
        int warp = threadIdx.x >> 5, lane = threadIdx.x & 31;
        if (lane == 0) {
            s_red[warp][0] = s0; s_red[warp][1] = s1;
            s_red[warp][2] = s2; s_red[warp][3] = s3;
        }
        __syncthreads();
        if (threadIdx.x < 4) {
            float v = s_red[0][threadIdx.x] + s_red[1][threadIdx.x]
                    + s_red[2][threadIdx.x] + s_red[3][threadIdx.x];
            int qk = ch / 48, cc = ch - qk*48;
            atomicAdd(&g_sq[((b*2 + qk)*48 + cc)*16 + (y & 3)*4 + threadIdx.x], v);
        }
    }
}

// ---------------- gram via mma.sync bf16 hi/lo split --------------------------
#define GT_STRIDE 72
#define GT_WORDS  36
#define GT_BYTES  (96*GT_STRIDE*2)
#define OFF_QH 0
#define OFF_QL GT_BYTES
#define OFF_KH (2*GT_BYTES)
#define OFF_KL (3*GT_BYTES)
#define GRAM_SMEM (4*GT_BYTES)

__global__ __launch_bounds__(192) void k_gram_mma() {
    extern __shared__ char smem[];
    uint32_t* sw = (uint32_t*)smem;
    const int tid  = threadIdx.x;
    const int wid  = tid >> 5, lane = tid & 31;
    const int split = blockIdx.x;
    const int bh = blockIdx.y;
    const int b = bh >> 3, h = bh & 7;
    const float* qbase = g_dwo + (size_t)(b*144      + h*6) * HW;
    const float* kbase = g_dwo + (size_t)(b*144 + 48 + h*6) * HW;

    float acc[12][4];
#pragma unroll
    for (int t = 0; t < 12; t++)
#pragma unroll
        for (int i = 0; i < 4; i++) acc[t][i] = 0.f;

    const int g4 = lane >> 2;
    const int q4 = lane & 3;

#pragma unroll 1
    for (int chunk = 0; chunk < 8; chunk++) {
        const int n0 = split*512 + chunk*64;
        const int hb = n0 >> 7, wb = n0 & 127;

        if (chunk > 0) __syncthreads();
#pragma unroll
        for (int i = 0; i < 16; i++) {
            int u = tid + i*192;
            int side = (u >= 1536) ? 1 : 0;
            int rem = u - side*1536;
            int j = rem & 63, g = rem >> 6;
            int ci = g >> 2, phy = g & 3;
            const float* bp = side ? kbase : qbase;
            float4 v4 = *(const float4*)(bp + (size_t)ci*HW
                                            + (size_t)(4*hb + phy)*512 + 4*(wb + j));
            __nv_bfloat16* th = (__nv_bfloat16*)(smem + (side ? OFF_KH : OFF_QH));
            __nv_bfloat16* tl = (__nv_bfloat16*)(smem + (side ? OFF_KL : OFF_QL));
            int r0 = ci*16 + phy*4;
            float vv[4] = {v4.x, v4.y, v4.z, v4.w};
#pragma unroll
            for (int p = 0; p < 4; p++) {
                float v = vv[p];
                __nv_bfloat16 hi = __float2bfloat16(v);
                __nv_bfloat16 lo = __float2bfloat16(v - __bfloat162float(hi));
                th[(r0 + p)*GT_STRIDE + j] = hi;
                tl[(r0 + p)*GT_STRIDE + j] = lo;
            }
        }
        __syncthreads();

        const uint32_t* qh = sw + (OFF_QH >> 2);
        const uint32_t* ql = sw + (OFF_QL >> 2);
        const uint32_t* kh = sw + (OFF_KH >> 2);
        const uint32_t* kl = sw + (OFF_KL >> 2);
        const int arow = wid*16 + g4;
#pragma unroll
        for (int ks = 0; ks < 4; ks++) {
            const int kw = ks*8 + q4;
            uint32_t Ah[4], Al[4];
            Ah[0] = qh[ arow     *GT_WORDS + kw    ];
            Ah[1] = qh[(arow + 8)*GT_WORDS + kw    ];
            Ah[2] = qh[ arow     *GT_WORDS + kw + 4];
            Ah[3] = qh[(arow + 8)*GT_WORDS + kw + 4];
            Al[0] = ql[ arow     *GT_WORDS + kw    ];
            Al[1] = ql[(arow + 8)*GT_WORDS + kw    ];
            Al[2] = ql[ arow     *GT_WORDS + kw + 4];
            Al[3] = ql[(arow + 8)*GT_WORDS + kw + 4];
#pragma unroll
            for (int nt = 0; nt < 12; nt++) {
                const int nrow = nt*8 + g4;
                uint32_t Bh[2], Bl[2];
                Bh[0] = kh[nrow*GT_WORDS + kw    ];
                Bh[1] = kh[nrow*GT_WORDS + kw + 4];
                Bl[0] = kl[nrow*GT_WORDS + kw    ];
                Bl[1] = kl[nrow*GT_WORDS + kw + 4];
                mma16816(acc[nt], Ah, Bh);
                mma16816(acc[nt], Ah, Bl);
                mma16816(acc[nt], Al, Bh);
            }
        }
    }

    float* gp = g_gsplit + (size_t)(split*16 + bh)*96*96;
    const int r0 = wid*16 + g4;
#pragma unroll
    for (int nt = 0; nt < 12; nt++) {
        const int c = nt*8 + q4*2;
        *(float2*)(gp + (size_t) r0     *96 + c) = make_float2(acc[nt][0], acc[nt][1]);
        *(float2*)(gp + (size_t)(r0 + 8)*96 + c) = make_float2(acc[nt][2], acc[nt][3]);
    }
}

// ---------------- softmax -> bf16 hi/lo attention, row-major [r][d] -----------
__global__ __launch_bounds__(256) void k_soft(const float* __restrict__ temp) {
    const int warp = blockIdx.x * 8 + (threadIdx.x >> 5);
    const int lane = threadIdx.x & 31;
    const int r = warp % 96, bh = warp / 96;
    const int b = bh >> 3, h = bh & 7;
    const float t = temp[h];
    float sqq = g_sq[((b*2 + 0)*48 + h*6 + (r >> 4))*16 + (r & 15)];
    const float invq = 1.f / fmaxf(sqrtf(sqq), 1e-12f);

    float v[3];
    float mx = -1e30f;
#pragma unroll
    for (int j = 0; j < 3; j++) {
        int d = lane + j*32;
        float g = 0.f;
#pragma unroll 4
        for (int s = 0; s < 32; s++)
            g += g_gsplit[((size_t)(s*16 + bh)*96 + r)*96 + d];
        float sqk = g_sq[((b*2 + 1)*48 + h*6 + (d >> 4))*16 + (d & 15)];
        float invk = 1.f / fmaxf(sqrtf(sqk), 1e-12f);
        v[j] = g * invq * invk * t;
        mx = fmaxf(mx, v[j]);
    }
#pragma unroll
    for (int o = 16; o > 0; o >>= 1) mx = fmaxf(mx, __shfl_xor_sync(0xffffffffu, mx, o));
    float sum = 0.f;
#pragma unroll
    for (int j = 0; j < 3; j++) { v[j] = __expf(v[j] - mx); sum += v[j]; }
#pragma unroll
    for (int o = 16; o > 0; o >>= 1) sum += __shfl_xor_sync(0xffffffffu, sum, o);
    float inv = 1.f / sum;
    __nv_bfloat16* ah = g_attn_h + (size_t)bh*96*96 + (size_t)r*96;
    __nv_bfloat16* al = g_attn_l + (size_t)bh*96*96 + (size_t)r*96;
#pragma unroll
    for (int j = 0; j < 3; j++) {
        int d = lane + j*32;
        float a = v[j] * inv;
        __nv_bfloat16 hi = __float2bfloat16(a);
        ah[d] = hi;
        al[d] = __float2bfloat16(a - __bfloat162float(hi));
    }
}

// ---------------- attn @ v via mma.sync (hi/lo split) -------------------------
#define APW 52
#define AV_AH 0
#define AV_AL (96*APW)
#define AV_VH (2*96*APW)
#define AV_VL (2*96*APW + 128*APW)
#define AV_SMEM ((2*96*APW + 2*128*APW)*4)

__global__ __launch_bounds__(192) void k_attnv_mma() {
    extern __shared__ uint32_t swa[];
    const int tid = threadIdx.x;
    const int wid = tid >> 5, lane = tid & 31;
    const int hb = blockIdx.x;
    const int bh = blockIdx.y;
    const int b = bh >> 3, h = bh & 7;
    const float* vbase = g_dwo + (size_t)(b*144 + 96 + h*6) * HW;

    {
        const uint32_t* srcH = (const uint32_t*)(g_attn_h + (size_t)bh*96*96);
        const uint32_t* srcL = (const uint32_t*)(g_attn_l + (size_t)bh*96*96);
        for (int i = tid; i < 96*48; i += 192) {
            int row = i / 48, w = i - row*48;
            swa[AV_AH + row*APW + w] = srcH[i];
            swa[AV_AL + row*APW + w] = srcL[i];
        }
    }
    for (int i = tid; i < 3072; i += 192) {
        int j = i & 127, g = i >> 7;
        int ci = g >> 2, phy = g & 3;
        float4 v4 = *(const float4*)(vbase + (size_t)ci*HW
                                        + (size_t)(4*hb + phy)*512 + 4*j);
        __nv_bfloat16 h0 = __float2bfloat16(v4.x);
        __nv_bfloat16 h1 = __float2bfloat16(v4.y);
        __nv_bfloat16 h2 = __float2bfloat16(v4.z);
        __nv_bfloat16 h3 = __float2bfloat16(v4.w);
        uint32_t hA = (uint32_t)__bfloat16_as_ushort(h0)
                    | ((uint32_t)__bfloat16_as_ushort(h1) << 16);
        uint32_t hB = (uint32_t)__bfloat16_as_ushort(h2)
                    | ((uint32_t)__bfloat16_as_ushort(h3) << 16);
        uint32_t lA = pack_bf16x2(v4.x - __bfloat162float(h0),
                                  v4.y - __bfloat162float(h1));
        uint32_t lB = pack_bf16x2(v4.z - __bfloat162float(h2),
                                  v4.w - __bfloat162float(h3));
        int w0 = j*APW + (ci*16 + phy*4)/2;
        swa[AV_VH + w0] = hA; swa[AV_VH + w0 + 1] = hB;
        swa[AV_VL + w0] = lA; swa[AV_VL + w0 + 1] = lB;
    }
    __syncthreads();

    const int g4 = lane >> 2, q4 = lane & 3;
    const int arow = wid*16 + g4;

    float acc[16][4];
#pragma unroll
    for (int t = 0; t < 16; t++)
#pragma unroll
        for (int i = 0; i < 4; i++) acc[t][i] = 0.f;

#pragma unroll
    for (int ks = 0; ks < 6; ks++) {
        const int kw = ks*8 + q4;
        uint32_t Ah[4], Al[4];
        Ah[0] = swa[AV_AH +  arow     *APW + kw    ];
        Ah[1] = swa[AV_AH + (arow + 8)*APW + kw    ];
        Ah[2] = swa[AV_AH +  arow     *APW + kw + 4];
        Ah[3] = swa[AV_AH + (arow + 8)*APW + kw + 4];
        Al[0] = swa[AV_AL +  arow     *APW + kw    ];
        Al[1] = swa[AV_AL + (arow + 8)*APW + kw    ];
        Al[2] = swa[AV_AL +  arow     *APW + kw + 4];
        Al[3] = swa[AV_AL + (arow + 8)*APW + kw + 4];
#pragma unroll
        for (int nt = 0; nt < 16; nt++) {
            const int nrow = nt*8 + g4;
            uint32_t Bh[2], Bl[2];
            Bh[0] = swa[AV_VH + nrow*APW + kw    ];
            Bh[1] = swa[AV_VH + nrow*APW + kw + 4];
            Bl[0] = swa[AV_VL + nrow*APW + kw    ];
            Bl[1] = swa[AV_VL + nrow*APW + kw + 4];
            mma16816(acc[nt], Ah, Bh);
            mma16816(acc[nt], Ah, Bl);
            mma16816(acc[nt], Al, Bh);
        }
    }

    __syncthreads();
    float* so = (float*)(swa + AV_VH);
#pragma unroll
    for (int nt = 0; nt < 16; nt++) {
        const int n0 = nt*8 + q4*2;
        so[ n0     *104 + arow    ] = acc[nt][0];
        so[(n0 + 1)*104 + arow    ] = acc[nt][1];
        so[ n0     *104 + arow + 8] = acc[nt][2];
        so[(n0 + 1)*104 + arow + 8] = acc[nt][3];
    }
    __syncthreads();

    if (tid < 128) {
        const int j = tid;
        const int W0 = 4*j;
        float* obase = g_ao + (size_t)(b*48 + h*6) * HW;
#pragma unroll
        for (int ci = 0; ci < 6; ci++)
#pragma unroll
            for (int nh = 0; nh < 4; nh++) {
                float4 v = *(float4*)&so[j*104 + ci*16 + nh*4];
                *(float4*)(obase + (size_t)ci*HW + (size_t)(4*hb + nh)*512 + W0) = v;
            }
    }
}

// ---------------- launch -----------------------------------------------------
extern "C" void kernel_launch(void* const* d_in, const int* in_sizes, int n_in,
                              void* d_out, int out_size) {
    const float* x      = (const float*)d_in[0];
    const float* qkv_w  = (const float*)d_in[1];
    const float* dw_w   = (const float*)d_in[2];
    const float* proj_w = (const float*)d_in[3];
    const float* temp   = (const float*)d_in[4];
    float* out = (float*)d_out;
    (void)in_sizes; (void)n_in; (void)out_size;

    void* p_ao;
    cudaGetSymbolAddress(&p_ao, g_ao);

    cudaFuncSetAttribute(k_gram_mma,  cudaFuncAttributeMaxDynamicSharedMemorySize, GRAM_SMEM);
    cudaFuncSetAttribute(k_conv_slab, cudaFuncAttributeMaxDynamicSharedMemorySize, CONV_SMEM);
    cudaFuncSetAttribute(k_attnv_mma, cudaFuncAttributeMaxDynamicSharedMemorySize, AV_SMEM);

    k_zero<<<12, 256>>>();
    for (int slab = 0; slab < 8; slab++) {
        k_conv_slab<<<dim3(132, 2), 288, CONV_SMEM>>>(x, qkv_w, slab);
        k_dw_slab<<<dim3(64, 144, 2), 128>>>(dw_w, slab);
    }
    k_gram_mma<<<dim3(32, 16), 192, GRAM_SMEM>>>();
    k_soft<<<192, 256>>>(temp);
    k_attnv_mma<<<dim3(128, 16), 192, AV_SMEM>>>();
    k_conv1x1<<<dim3(2048, 1, 2), 128>>>((const float*)p_ao, proj_w, out, 48);
}

// round 16
// speedup vs baseline: 1.1782x; 1.1782x over previous
#include <cuda_runtime.h>
#include <cuda_bf16.h>
#include <cuda_fp16.h>
#include <math.h>
#include <stdint.h>

#define HW 262144   // 512*512
typedef unsigned long long u64;

// ---------------- packed f32x2 helpers (sm_103a FFMA2) ------------------------
__device__ __forceinline__ u64 pk(float lo, float hi) {
    u64 r;
    asm("mov.b64 %0, {%1, %2};" : "=l"(r) : "f"(lo), "f"(hi));
    return r;
}
__device__ __forceinline__ void fma2(u64& d, u64 a, u64 b) {
    asm("fma.rn.f32x2 %0, %1, %2, %0;" : "+l"(d) : "l"(a), "l"(b));
}
__device__ __forceinline__ float2 upk(u64 v) {
    float2 f;
    asm("mov.b64 {%0, %1}, %2;" : "=f"(f.x), "=f"(f.y) : "l"(v));
    return f;
}

// ---------------- mma.sync helper (bf16, fp32 accum) --------------------------
__device__ __forceinline__ void mma16816(float* c, const uint32_t* a, const uint32_t* b) {
    asm volatile(
        "mma.sync.aligned.m16n8k16.row.col.f32.bf16.bf16.f32 "
        "{%0,%1,%2,%3}, {%4,%5,%6,%7}, {%8,%9}, {%0,%1,%2,%3};"
        : "+f"(c[0]), "+f"(c[1]), "+f"(c[2]), "+f"(c[3])
        : "r"(a[0]), "r"(a[1]), "r"(a[2]), "r"(a[3]), "r"(b[0]), "r"(b[1]));
}
__device__ __forceinline__ uint32_t pack_bf16x2(float a, float b) {
    return (uint32_t)__bfloat16_as_ushort(__float2bfloat16(a))
         | ((uint32_t)__bfloat16_as_ushort(__float2bfloat16(b)) << 16);
}

// ---------------- scratch (device globals; no allocation allowed) -------------
__device__ __half g_qkv [2*144*HW];     // after 1x1 conv (fp16, 151 MB)
__device__ __half g_dwo [2*144*HW];     // after depthwise 3x3 (fp16)
__device__ float g_ao   [2*48*HW];      // attn @ v, image layout
__device__ float g_sq   [2*2*48*16];    // sum of squares: [b][q/k][ch][phase]
__device__ float g_gsplit[32*16*96*96]; // per-split partial grams
__device__ __nv_bfloat16 g_attn_h[16*96*96];  // softmaxed attn hi [r][d]
__device__ __nv_bfloat16 g_attn_l[16*96*96];  // softmaxed attn lo

// ---------------- zero sum-of-squares accumulator -----------------------------
__global__ void k_zero() {
    int i = blockIdx.x * 256 + threadIdx.x;
    if (i < 2*2*48*16) g_sq[i] = 0.f;
}

// ---------------- qkv 1x1 conv via mma.sync (hi/lo split W and X) -------------
// grid (1024, 2), block 288 (9 warps = 9 oc-tiles of 16).  N = 256 px per CTA.
#define CPW 28
#define C_WH 0
#define C_WL (144*CPW)
#define C_XH (2*144*CPW)
#define C_XL (2*144*CPW + 256*CPW)
#define CONV_SMEM ((2*144*CPW + 2*256*CPW)*4)  // 89600 bytes

__global__ __launch_bounds__(288) void k_conv_mma(const float* __restrict__ x,
                                                  const float* __restrict__ wgt) {
    extern __shared__ uint32_t swc[];
    const int tid = threadIdx.x;
    const int wid = tid >> 5, lane = tid & 31;
    const int px0 = blockIdx.x * 256;
    const int b   = blockIdx.y;
    const float* inb = x + (size_t)b * 48 * HW;

    {
        __nv_bfloat16* wh = (__nv_bfloat16*)(swc + C_WH);
        __nv_bfloat16* wl = (__nv_bfloat16*)(swc + C_WL);
        for (int i = tid; i < 144*48; i += 288) {
            int oc = i / 48, ci = i - oc*48;
            float v = wgt[i];
            __nv_bfloat16 hi = __float2bfloat16(v);
            wh[oc*(2*CPW) + ci] = hi;
            wl[oc*(2*CPW) + ci] = __float2bfloat16(v - __bfloat162float(hi));
        }
    }
    {
        __nv_bfloat16* xh = (__nv_bfloat16*)(swc + C_XH);
        __nv_bfloat16* xl = (__nv_bfloat16*)(swc + C_XL);
        for (int i = tid; i < 48*64; i += 288) {
            int ch = i >> 6, p4 = i & 63;
            float4 v4 = ((const float4*)(inb + (size_t)ch*HW + px0))[p4];
            float vv[4] = {v4.x, v4.y, v4.z, v4.w};
#pragma unroll
            for (int t = 0; t < 4; t++) {
                float v = vv[t];
                __nv_bfloat16 hi = __float2bfloat16(v);
                xh[(p4*4 + t)*(2*CPW) + ch] = hi;
                xl[(p4*4 + t)*(2*CPW) + ch] = __float2bfloat16(v - __bfloat162float(hi));
            }
        }
    }
    __syncthreads();

    const int g4 = lane >> 2, q4 = lane & 3;
    const int arow = wid*16 + g4;

#pragma unroll 1
    for (int half = 0; half < 2; half++) {
        float acc[16][4];
#pragma unroll
        for (int t = 0; t < 16; t++)
#pragma unroll
            for (int i = 0; i < 4; i++) acc[t][i] = 0.f;

#pragma unroll
        for (int ks = 0; ks < 3; ks++) {
            const int kw = ks*8 + q4;
            uint32_t Ah[4], Al[4];
            Ah[0] = swc[C_WH +  arow     *CPW + kw    ];
            Ah[1] = swc[C_WH + (arow + 8)*CPW + kw    ];
            Ah[2] = swc[C_WH +  arow     *CPW + kw + 4];
            Ah[3] = swc[C_WH + (arow + 8)*CPW + kw + 4];
            Al[0] = swc[C_WL +  arow     *CPW + kw    ];
            Al[1] = swc[C_WL + (arow + 8)*CPW + kw    ];
            Al[2] = swc[C_WL +  arow     *CPW + kw + 4];
            Al[3] = swc[C_WL + (arow + 8)*CPW + kw + 4];
#pragma unroll
            for (int nt = 0; nt < 16; nt++) {
                const int nrow = (half*16 + nt)*8 + g4;
                uint32_t Bh[2], Bl[2];
                Bh[0] = swc[C_XH + nrow*CPW + kw    ];
                Bh[1] = swc[C_XH + nrow*CPW + kw + 4];
                Bl[0] = swc[C_XL + nrow*CPW + kw    ];
                Bl[1] = swc[C_XL + nrow*CPW + kw + 4];
                mma16816(acc[nt], Ah, Bh);
                mma16816(acc[nt], Ah, Bl);
                mma16816(acc[nt], Al, Bh);
            }
        }
#pragma unroll
        for (int nt = 0; nt < 16; nt++) {
            const int col = px0 + (half*16 + nt)*8 + q4*2;
            __half* o1 = g_qkv + ((size_t)b*144 + arow)*HW + col;
            *(__half2*)o1 = __floats2half2_rn(acc[nt][0], acc[nt][1]);
            *(__half2*)(o1 + (size_t)8*HW) = __floats2half2_rn(acc[nt][2], acc[nt][3]);
        }
    }
}

// ---------------- 1x1 conv as SGEMM (f32x2) — used for proj -------------------
__global__ __launch_bounds__(128) void k_conv1x1(const float* __restrict__ in,
                                                 const float* __restrict__ wgt,
                                                 float* __restrict__ out,
                                                 int ocTot) {
    __shared__ __align__(16) float s_x[48*128];
    __shared__ float s_w[48*48];
    const int tid = threadIdx.x;
    const int px0 = blockIdx.x * 128;
    const int ocb = blockIdx.y * 48;
    const int b   = blockIdx.z;
    const float* inb = in + (size_t)b * 48 * HW;

    for (int i = tid; i < 48*48; i += 128) {
        int oc = i / 48, ci = i - oc*48;
        s_w[ci*48 + oc] = wgt[(ocb + oc)*48 + ci];
    }
    for (int i = tid; i < 48*32; i += 128) {
        int ci = i >> 5, p4 = i & 31;
        ((float4*)s_x)[i] = ((const float4*)(inb + (size_t)ci*HW + px0))[p4];
    }
    __syncthreads();

    const int ty = tid >> 4, tx = tid & 15;
    u64 acc2[6][4];
#pragma unroll
    for (int i = 0; i < 6; i++)
#pragma unroll
        for (int j = 0; j < 4; j++) acc2[i][j] = pk(0.f, 0.f);

    for (int ci = 0; ci < 48; ci++) {
        u64 wp[6], xv[4];
#pragma unroll
        for (int i = 0; i < 6; i++) {
            float wv = s_w[ci*48 + ty*6 + i];
            wp[i] = pk(wv, wv);
        }
#pragma unroll
        for (int j = 0; j < 4; j++)
            xv[j] = *(const u64*)&s_x[ci*128 + tx*2 + j*32];
#pragma unroll
        for (int i = 0; i < 6; i++)
#pragma unroll
            for (int j = 0; j < 4; j++) fma2(acc2[i][j], wp[i], xv[j]);
    }

#pragma unroll
    for (int i = 0; i < 6; i++) {
        float* op = out + ((size_t)b*ocTot + ocb + ty*6 + i)*HW + px0;
#pragma unroll
        for (int j = 0; j < 4; j++)
            *(float2*)(op + tx*2 + j*32) = upk(acc2[i][j]);
    }
}

// ---------------- depthwise 3x3: 4 rows/CTA, fp16 in/out, fused norms ---------
// grid (128, 144, 2), block 128
__global__ __launch_bounds__(128) void k_dw4(const float* __restrict__ dww) {
    __shared__ float s_red[4][16];
    const int y0 = blockIdx.x * 4;
    const int ch = blockIdx.y;
    const int b  = blockIdx.z;
    const __half* in  = g_qkv + (size_t)(b*144 + ch) * HW;
    __half*       out = g_dwo + (size_t)(b*144 + ch) * HW;
    float w[9];
#pragma unroll
    for (int i = 0; i < 9; i++) w[i] = dww[ch*9 + i];

    const int x4 = threadIdx.x * 4;
    float c[6][4], l[6], r[6];
#pragma unroll
    for (int i = 0; i < 6; i++) {
        int yy = y0 - 1 + i;
        if (yy < 0 || yy > 511) {
            c[i][0] = c[i][1] = c[i][2] = c[i][3] = 0.f;
            l[i] = r[i] = 0.f;
        } else {
            const __half* row = in + yy*512;
            uint2 raw = *(const uint2*)(row + x4);
            __half2 pA = *reinterpret_cast<__half2*>(&raw.x);
            __half2 pB = *reinterpret_cast<__half2*>(&raw.y);
            c[i][0] = __low2float(pA);  c[i][1] = __high2float(pA);
            c[i][2] = __low2float(pB);  c[i][3] = __high2float(pB);
            l[i] = (x4 > 0)   ? __half2float(row[x4 - 1]) : 0.f;
            r[i] = (x4 < 508) ? __half2float(row[x4 + 4]) : 0.f;
        }
    }

    float sq[16];
#pragma unroll
    for (int oy = 0; oy < 4; oy++) {
        float o0 = 0.f, o1 = 0.f, o2 = 0.f, o3 = 0.f;
#pragma unroll
        for (int dy = 0; dy < 3; dy++) {
            const int i = oy + dy;
            float w0 = w[dy*3], w1 = w[dy*3 + 1], w2 = w[dy*3 + 2];
            o0 += w0*l[i]    + w1*c[i][0] + w2*c[i][1];
            o1 += w0*c[i][0] + w1*c[i][1] + w2*c[i][2];
            o2 += w0*c[i][1] + w1*c[i][2] + w2*c[i][3];
            o3 += w0*c[i][2] + w1*c[i][3] + w2*r[i];
        }
        __half2 hA = __floats2half2_rn(o0, o1);
        __half2 hB = __floats2half2_rn(o2, o3);
        uint2 raw;
        *reinterpret_cast<__half2*>(&raw.x) = hA;
        *reinterpret_cast<__half2*>(&raw.y) = hB;
        *(uint2*)(out + (y0 + oy)*512 + x4) = raw;
        sq[oy*4 + 0] = o0*o0; sq[oy*4 + 1] = o1*o1;
        sq[oy*4 + 2] = o2*o2; sq[oy*4 + 3] = o3*o3;
    }

    if (ch < 96) {
#pragma unroll
        for (int p = 0; p < 16; p++)
#pragma unroll
            for (int o = 16; o > 0; o >>= 1)
                sq[p] += __shfl_xor_sync(0xffffffffu, sq[p], o);
        int warp = threadIdx.x >> 5, lane = threadIdx.x & 31;
        if (lane == 0)
#pragma unroll
            for (int p = 0; p < 16; p++) s_red[warp][p] = sq[p];
        __syncthreads();
        if (threadIdx.x < 16) {
            float v = s_red[0][threadIdx.x] + s_red[1][threadIdx.x]
                    + s_red[2][threadIdx.x] + s_red[3][threadIdx.x];
            int qk = ch / 48, cc = ch - qk*48;
            atomicAdd(&g_sq[((b*2 + qk)*48 + cc)*16 + threadIdx.x], v);
        }
    }
}

// ---------------- gram via mma.sync bf16 hi/lo split (fp16 source) ------------
#define GT_STRIDE 72
#define GT_WORDS  36
#define GT_BYTES  (96*GT_STRIDE*2)
#define OFF_QH 0
#define OFF_QL GT_BYTES
#define OFF_KH (2*GT_BYTES)
#define OFF_KL (3*GT_BYTES)
#define GRAM_SMEM (4*GT_BYTES)

__global__ __launch_bounds__(192) void k_gram_mma() {
    extern __shared__ char smem[];
    uint32_t* sw = (uint32_t*)smem;
    const int tid  = threadIdx.x;
    const int wid  = tid >> 5, lane = tid & 31;
    const int split = blockIdx.x;
    const int bh = blockIdx.y;
    const int b = bh >> 3, h = bh & 7;
    const __half* qbase = g_dwo + (size_t)(b*144      + h*6) * HW;
    const __half* kbase = g_dwo + (size_t)(b*144 + 48 + h*6) * HW;

    float acc[12][4];
#pragma unroll
    for (int t = 0; t < 12; t++)
#pragma unroll
        for (int i = 0; i < 4; i++) acc[t][i] = 0.f;

    const int g4 = lane >> 2;
    const int q4 = lane & 3;

#pragma unroll 1
    for (int chunk = 0; chunk < 8; chunk++) {
        const int n0 = split*512 + chunk*64;
        const int hb = n0 >> 7, wb = n0 & 127;

        if (chunk > 0) __syncthreads();
#pragma unroll
        for (int i = 0; i < 16; i++) {
            int u = tid + i*192;
            int side = (u >= 1536) ? 1 : 0;
            int rem = u - side*1536;
            int j = rem & 63, g = rem >> 6;
            int ci = g >> 2, phy = g & 3;
            const __half* bp = side ? kbase : qbase;
            uint2 raw = *(const uint2*)(bp + (size_t)ci*HW
                                           + (size_t)(4*hb + phy)*512 + 4*(wb + j));
            __half2 pA = *reinterpret_cast<__half2*>(&raw.x);
            __half2 pB = *reinterpret_cast<__half2*>(&raw.y);
            float vv[4] = {__low2float(pA), __high2float(pA),
                           __low2float(pB), __high2float(pB)};
            __nv_bfloat16* th = (__nv_bfloat16*)(smem + (side ? OFF_KH : OFF_QH));
            __nv_bfloat16* tl = (__nv_bfloat16*)(smem + (side ? OFF_KL : OFF_QL));
            int r0 = ci*16 + phy*4;
#pragma unroll
            for (int p = 0; p < 4; p++) {
                float v = vv[p];
                __nv_bfloat16 hi = __float2bfloat16(v);
                __nv_bfloat16 lo = __float2bfloat16(v - __bfloat162float(hi));
                th[(r0 + p)*GT_STRIDE + j] = hi;
                tl[(r0 + p)*GT_STRIDE + j] = lo;
            }
        }
        __syncthreads();

        const uint32_t* qh = sw + (OFF_QH >> 2);
        const uint32_t* ql = sw + (OFF_QL >> 2);
        const uint32_t* kh = sw + (OFF_KH >> 2);
        const uint32_t* kl = sw + (OFF_KL >> 2);
        const int arow = wid*16 + g4;
#pragma unroll
        for (int ks = 0; ks < 4; ks++) {
            const int kw = ks*8 + q4;
            uint32_t Ah[4], Al[4];
            Ah[0] = qh[ arow     *GT_WORDS + kw    ];
            Ah[1] = qh[(arow + 8)*GT_WORDS + kw    ];
            Ah[2] = qh[ arow     *GT_WORDS + kw + 4];
            Ah[3] = qh[(arow + 8)*GT_WORDS + kw + 4];
            Al[0] = ql[ arow     *GT_WORDS + kw    ];
            Al[1] = ql[(arow + 8)*GT_WORDS + kw    ];
            Al[2] = ql[ arow     *GT_WORDS + kw + 4];
            Al[3] = ql[(arow + 8)*GT_WORDS + kw + 4];
#pragma unroll
            for (int nt = 0; nt < 12; nt++) {
                const int nrow = nt*8 + g4;
                uint32_t Bh[2], Bl[2];
                Bh[0] = kh[nrow*GT_WORDS + kw    ];
                Bh[1] = kh[nrow*GT_WORDS + kw + 4];
                Bl[0] = kl[nrow*GT_WORDS + kw    ];
                Bl[1] = kl[nrow*GT_WORDS + kw + 4];
                mma16816(acc[nt], Ah, Bh);
                mma16816(acc[nt], Ah, Bl);
                mma16816(acc[nt], Al, Bh);
            }
        }
    }

    float* gp = g_gsplit + (size_t)(split*16 + bh)*96*96;
    const int r0 = wid*16 + g4;
#pragma unroll
    for (int nt = 0; nt < 12; nt++) {
        const int c = nt*8 + q4*2;
        *(float2*)(gp + (size_t) r0     *96 + c) = make_float2(acc[nt][0], acc[nt][1]);
        *(float2*)(gp + (size_t)(r0 + 8)*96 + c) = make_float2(acc[nt][2], acc[nt][3]);
    }
}

// ---------------- softmax -> bf16 hi/lo attention, row-major [r][d] -----------
__global__ __launch_bounds__(256) void k_soft(const float* __restrict__ temp) {
    const int warp = blockIdx.x * 8 + (threadIdx.x >> 5);
    const int lane = threadIdx.x & 31;
    const int r = warp % 96, bh = warp / 96;
    const int b = bh >> 3, h = bh & 7;
    const float t = temp[h];
    float sqq = g_sq[((b*2 + 0)*48 + h*6 + (r >> 4))*16 + (r & 15)];
    const float invq = 1.f / fmaxf(sqrtf(sqq), 1e-12f);

    float v[3];
    float mx = -1e30f;
#pragma unroll
    for (int j = 0; j < 3; j++) {
        int d = lane + j*32;
        float g = 0.f;
#pragma unroll 4
        for (int s = 0; s < 32; s++)
            g += g_gsplit[((size_t)(s*16 + bh)*96 + r)*96 + d];
        float sqk = g_sq[((b*2 + 1)*48 + h*6 + (d >> 4))*16 + (d & 15)];
        float invk = 1.f / fmaxf(sqrtf(sqk), 1e-12f);
        v[j] = g * invq * invk * t;
        mx = fmaxf(mx, v[j]);
    }
#pragma unroll
    for (int o = 16; o > 0; o >>= 1) mx = fmaxf(mx, __shfl_xor_sync(0xffffffffu, mx, o));
    float sum = 0.f;
#pragma unroll
    for (int j = 0; j < 3; j++) { v[j] = __expf(v[j] - mx); sum += v[j]; }
#pragma unroll
    for (int o = 16; o > 0; o >>= 1) sum += __shfl_xor_sync(0xffffffffu, sum, o);
    float inv = 1.f / sum;
    __nv_bfloat16* ah = g_attn_h + (size_t)bh*96*96 + (size_t)r*96;
    __nv_bfloat16* al = g_attn_l + (size_t)bh*96*96 + (size_t)r*96;
#pragma unroll
    for (int j = 0; j < 3; j++) {
        int d = lane + j*32;
        float a = v[j] * inv;
        __nv_bfloat16 hi = __float2bfloat16(a);
        ah[d] = hi;
        al[d] = __float2bfloat16(a - __bfloat162float(hi));
    }
}

// ---------------- attn @ v via mma.sync (hi/lo split, fp16 v source) ----------
#define APW 52
#define AV_AH 0
#define AV_AL (96*APW)
#define AV_VH (2*96*APW)
#define AV_VL (2*96*APW + 128*APW)
#define AV_SMEM ((2*96*APW + 2*128*APW)*4)

__global__ __launch_bounds__(192) void k_attnv_mma() {
    extern __shared__ uint32_t swa[];
    const int tid = threadIdx.x;
    const int wid = tid >> 5, lane = tid & 31;
    const int hb = blockIdx.x;
    const int bh = blockIdx.y;
    const int b = bh >> 3, h = bh & 7;
    const __half* vbase = g_dwo + (size_t)(b*144 + 96 + h*6) * HW;

    {
        const uint32_t* srcH = (const uint32_t*)(g_attn_h + (size_t)bh*96*96);
        const uint32_t* srcL = (const uint32_t*)(g_attn_l + (size_t)bh*96*96);
        for (int i = tid; i < 96*48; i += 192) {
            int row = i / 48, w = i - row*48;
            swa[AV_AH + row*APW + w] = srcH[i];
            swa[AV_AL + row*APW + w] = srcL[i];
        }
    }
    for (int i = tid; i < 3072; i += 192) {
        int j = i & 127, g = i >> 7;
        int ci = g >> 2, phy = g & 3;
        uint2 raw = *(const uint2*)(vbase + (size_t)ci*HW
                                       + (size_t)(4*hb + phy)*512 + 4*j);
        __half2 pA = *reinterpret_cast<__half2*>(&raw.x);
        __half2 pB = *reinterpret_cast<__half2*>(&raw.y);
        float f0 = __low2float(pA), f1 = __high2float(pA);
        float f2 = __low2float(pB), f3 = __high2float(pB);
        __nv_bfloat16 h0 = __float2bfloat16(f0);
        __nv_bfloat16 h1 = __float2bfloat16(f1);
        __nv_bfloat16 h2 = __float2bfloat16(f2);
        __nv_bfloat16 h3 = __float2bfloat16(f3);
        uint32_t hA = (uint32_t)__bfloat16_as_ushort(h0)
                    | ((uint32_t)__bfloat16_as_ushort(h1) << 16);
        uint32_t hB = (uint32_t)__bfloat16_as_ushort(h2)
                    | ((uint32_t)__bfloat16_as_ushort(h3) << 16);
        uint32_t lA = pack_bf16x2(f0 - __bfloat162float(h0),
                                  f1 - __bfloat162float(h1));
        uint32_t lB = pack_bf16x2(f2 - __bfloat162float(h2),
                                  f3 - __bfloat162float(h3));
        int w0 = j*APW + (ci*16 + phy*4)/2;
        swa[AV_VH + w0] = hA; swa[AV_VH + w0 + 1] = hB;
        swa[AV_VL + w0] = lA; swa[AV_VL + w0 + 1] = lB;
    }
    __syncthreads();

    const int g4 = lane >> 2, q4 = lane & 3;
    const int arow = wid*16 + g4;

    float acc[16][4];
#pragma unroll
    for (int t = 0; t < 16; t++)
#pragma unroll
        for (int i = 0; i < 4; i++) acc[t][i] = 0.f;

#pragma unroll
    for (int ks = 0; ks < 6; ks++) {
        const int kw = ks*8 + q4;
        uint32_t Ah[4], Al[4];
        Ah[0] = swa[AV_AH +  arow     *APW + kw    ];
        Ah[1] = swa[AV_AH + (arow + 8)*APW + kw    ];
        Ah[2] = swa[AV_AH +  arow     *APW + kw + 4];
        Ah[3] = swa[AV_AH + (arow + 8)*APW + kw + 4];
        Al[0] = swa[AV_AL +  arow     *APW + kw    ];
        Al[1] = swa[AV_AL + (arow + 8)*APW + kw    ];
        Al[2] = swa[AV_AL +  arow     *APW + kw + 4];
        Al[3] = swa[AV_AL + (arow + 8)*APW + kw + 4];
#pragma unroll
        for (int nt = 0; nt < 16; nt++) {
            const int nrow = nt*8 + g4;
            uint32_t Bh[2], Bl[2];
            Bh[0] = swa[AV_VH + nrow*APW + kw    ];
            Bh[1] = swa[AV_VH + nrow*APW + kw + 4];
            Bl[0] = swa[AV_VL + nrow*APW + kw    ];
            Bl[1] = swa[AV_VL + nrow*APW + kw + 4];
            mma16816(acc[nt], Ah, Bh);
            mma16816(acc[nt], Ah, Bl);
            mma16816(acc[nt], Al, Bh);
        }
    }

    __syncthreads();
    float* so = (float*)(swa + AV_VH);
#pragma unroll
    for (int nt = 0; nt < 16; nt++) {
        const int n0 = nt*8 + q4*2;
        so[ n0     *104 + arow    ] = acc[nt][0];
        so[(n0 + 1)*104 + arow    ] = acc[nt][1];
        so[ n0     *104 + arow + 8] = acc[nt][2];
        so[(n0 + 1)*104 + arow + 8] = acc[nt][3];
    }
    __syncthreads();

    if (tid < 128) {
        const int j = tid;
        const int W0 = 4*j;
        float* obase = g_ao + (size_t)(b*48 + h*6) * HW;
#pragma unroll
        for (int ci = 0; ci < 6; ci++)
#pragma unroll
            for (int nh = 0; nh < 4; nh++) {
                float4 v = *(float4*)&so[j*104 + ci*16 + nh*4];
                *(float4*)(obase + (size_t)ci*HW + (size_t)(4*hb + nh)*512 + W0) = v;
            }
    }
}

// ---------------- launch -----------------------------------------------------
extern "C" void kernel_launch(void* const* d_in, const int* in_sizes, int n_in,
                              void* d_out, int out_size) {
    const float* x      = (const float*)d_in[0];
    const float* qkv_w  = (const float*)d_in[1];
    const float* dw_w   = (const float*)d_in[2];
    const float* proj_w = (const float*)d_in[3];
    const float* temp   = (const float*)d_in[4];
    float* out = (float*)d_out;
    (void)in_sizes; (void)n_in; (void)out_size;

    void* p_ao;
    cudaGetSymbolAddress(&p_ao, g_ao);

    cudaFuncSetAttribute(k_gram_mma,  cudaFuncAttributeMaxDynamicSharedMemorySize, GRAM_SMEM);
    cudaFuncSetAttribute(k_conv_mma,  cudaFuncAttributeMaxDynamicSharedMemorySize, CONV_SMEM);
    cudaFuncSetAttribute(k_attnv_mma, cudaFuncAttributeMaxDynamicSharedMemorySize, AV_SMEM);

    k_zero<<<12, 256>>>();
    k_conv_mma<<<dim3(1024, 2), 288, CONV_SMEM>>>(x, qkv_w);
    k_dw4<<<dim3(128, 144, 2), 128>>>(dw_w);
    k_gram_mma<<<dim3(32, 16), 192, GRAM_SMEM>>>();
    k_soft<<<192, 256>>>(temp);
    k_attnv_mma<<<dim3(128, 16), 192, AV_SMEM>>>();
    k_conv1x1<<<dim3(2048, 1, 2), 128>>>((const float*)p_ao, proj_w, out, 48);
}